// round 8
// baseline (speedup 1.0000x reference)
#include <cuda_runtime.h>
#include <cstdint>

#define HD   128
#define TS   512
#define BSZ  4096
#define CD   10
#define BT   32
#define NCTA (BSZ / BT)   // 128
#define NTHR 512          // 16 warps = 8 pairs; pair p owns cols 4p..4p+3
#define TPREF 128

// ---- shared memory layout (bytes) ----
#define SM_W    0                    // Ws[k][m], row 512B            : 64 KB
#define SM_X    (64 * 1024)          // xs[32][TPREF]                 : 16 KB
#define SM_HD   (80 * 1024)          // h dup (h,h)[2][32][128] pp    : 64 KB
#define SM_PART (144 * 1024)         // rowsum partials [4][128]      : 2 KB
#define SM_F    (SM_PART + 2048)     // sflag[32], deltabits, xmax, okpos
#define SM_SZ   (SM_F + 256)

typedef unsigned long long ull;

static __device__ __forceinline__ uint32_t smem_u32(const void* p) {
    uint32_t a;
    asm("{ .reg .u64 t; cvta.to.shared.u64 t, %1; cvt.u32.u64 %0, t; }" : "=r"(a) : "l"(p));
    return a;
}
static __device__ __forceinline__ ull pk(float lo, float hi) {
    ull r; asm("mov.b64 %0, {%1, %2};" : "=l"(r) : "f"(lo), "f"(hi)); return r;
}
static __device__ __forceinline__ void upk(ull v, float& lo, float& hi) {
    asm("mov.b64 {%0, %1}, %2;" : "=f"(lo), "=f"(hi) : "l"(v));
}
static __device__ __forceinline__ ull fma2(ull a, ull b, ull c) {
    ull d; asm("fma.rn.f32x2 %0, %1, %2, %3;" : "=l"(d) : "l"(a), "l"(b), "l"(c)); return d;
}
static __device__ __forceinline__ ull add2(ull a, ull b) {
    ull d; asm("add.rn.f32x2 %0, %1, %2;" : "=l"(d) : "l"(a), "l"(b)); return d;
}
// exactly +-1.0f for |x| >~ 9 (matches fp32 tanhf saturation); ~1e-7 abs err
static __device__ __forceinline__ float tanh_acc(float v) {
    float a = fabsf(v);
    float e = __expf(2.0f * a);
    float r = 1.0f - 2.0f / (e + 1.0f);
    return copysignf(r, v);
}
// W pair load {W[k][m],W[k][m+1]} — lane-strided 8B, conflict-free
#define WLOAD64(w, base, IMM) \
    asm volatile("ld.shared.b64 %0, [%1+" IMM "];" : "=l"(w) : "r"(base))
// dup-h load: two ready f32x2 operands (k, k+1) — broadcast, conflict-free
#define HLOAD(a, b, base, IMM) \
    asm volatile("ld.shared.v2.b64 {%0,%1}, [%2+" IMM "];" \
                 : "=l"(a), "=l"(b) : "r"(base))

// one k4 block: k = 4*k4g+q for this group's base; all offsets literal
#define K4(IW0, IW1, IW2, IW3, IH0, IH1, CHI)                           \
    {                                                                   \
        ull w0_, w1_, w2_, w3_;                                         \
        WLOAD64(w0_, wb, IW0); WLOAD64(w1_, wb, IW1);                   \
        WLOAD64(w2_, wb, IW2); WLOAD64(w3_, wb, IW3);                   \
        _Pragma("unroll")                                               \
        for (int j = 0; j < J; ++j) {                                   \
            ull ha_, hb_, hc_, hd_;                                     \
            HLOAD(ha_, hb_, hcb[j], IH0);                               \
            HLOAD(hc_, hd_, hcb[j], IH1);                               \
            constexpr int ch = (CH == 4) ? (CHI) : 0;                   \
            acc[j][ch] = fma2(w0_, ha_, acc[j][ch]);                    \
            acc[j][ch] = fma2(w1_, hb_, acc[j][ch]);                    \
            acc[j][ch] = fma2(w2_, hc_, acc[j][ch]);                    \
            acc[j][ch] = fma2(w3_, hd_, acc[j][ch]);                    \
        }                                                               \
    }

// epilogue: tanh, dup-pair STS.128 of this half's m-pair, threshold votes.
// am bits: j -> all v >= thr ; 8+j -> all v <= -thr  (uniform across warp)
template <int J>
static __device__ __forceinline__ unsigned
epilogue(const ull* acc, float* hwr, const int* cols, int mb, float thr)
{
    unsigned am = 0;
    #pragma unroll
    for (int j = 0; j < J; ++j) {
        float v0, v1; upk(acc[j], v0, v1);
        v0 = tanh_acc(v0); v1 = tanh_acc(v1);
        *(float4*)(hwr + (cols[j] * HD + mb) * 2) = make_float4(v0, v0, v1, v1);
        bool p = (v0 >=  thr) & (v1 >=  thr);
        bool n = (v0 <= -thr) & (v1 <= -thr);
        unsigned bp_ = __ballot_sync(0xffffffffu, p);
        unsigned bn_ = __ballot_sync(0xffffffffu, n);
        if (bp_ == 0xffffffffu) am |= 1u << j;
        if (bn_ == 0xffffffffu) am |= 1u << (8 + j);
    }
    return am;
}

// one step for J live columns; this warp covers m = mb, mb+1 (its half).
// J<=2: 4 accumulator chains (quartered tail latency).
template <int J>
static __device__ __forceinline__ unsigned
do_step(uint32_t wbase, uint32_t hrd, float* hwr, const int* cols,
        const float* xv, ull wx2, ull bh2, int mb, float thr)
{
    constexpr int CH = (J <= 2) ? 4 : 1;
    ull acc[J][CH];
    #pragma unroll
    for (int j = 0; j < J; ++j) {
        acc[j][0] = fma2(wx2, pk(xv[j], xv[j]), bh2);
        #pragma unroll
        for (int c = 1; c < CH; ++c) acc[j][c] = 0ull;
    }
    uint32_t wb = wbase;
    uint32_t hcb[J];
    #pragma unroll
    for (int j = 0; j < J; ++j) hcb[j] = hrd + (uint32_t)cols[j] * 1024u;

    #pragma unroll 2
    for (int g = 0; g < 8; ++g) {                 // 8 groups x 4 k4 = 32 k4
        K4("0",    "512",  "1024", "1536", "0",  "16",  0)
        K4("2048", "2560", "3072", "3584", "32", "48",  1)
        K4("4096", "4608", "5120", "5632", "64", "80",  2)
        K4("6144", "6656", "7168", "7680", "96", "112", 3)
        wb += 8192;
        #pragma unroll
        for (int j = 0; j < J; ++j) hcb[j] += 128;
    }
    ull fin[J];
    #pragma unroll
    for (int j = 0; j < J; ++j)
        fin[j] = (CH == 4) ? add2(add2(acc[j][0], acc[j][1]),
                                  add2(acc[j][2], acc[j][3]))
                           : acc[j][0];
    return epilogue<J>(fin, hwr, cols, mb, thr);
}

__global__ void __launch_bounds__(NTHR, 1)
rnn_kernel(const float* __restrict__ x,   const float* __restrict__ Whx,
           const float* __restrict__ Whh, const float* __restrict__ Wph,
           const float* __restrict__ bh,  const float* __restrict__ bp,
           float* __restrict__ out)
{
    extern __shared__ char sm[];
    float* Xs   = (float*)(sm + SM_X);
    float* Hd0  = (float*)(sm + SM_HD);            // dup layout, 32KB
    float* Hd1  = (float*)(sm + SM_HD + 32768);
    float* part = (float*)(sm + SM_PART);          // [4][128]
    unsigned* sflag     = (unsigned*)(sm + SM_F);  // [2][8][2]
    unsigned* deltabits = (unsigned*)(sm + SM_F + 128);
    unsigned* xmaxb     = (unsigned*)(sm + SM_F + 132);
    int*      okpos     = (int*)(sm + SM_F + 136);

    const int tid  = threadIdx.x;
    const int lane = tid & 31;
    const int wid  = tid >> 5;
    const int pair = wid >> 1;                 // 0..7: owns cols 4*pair..+3
    const int half = wid & 1;                  // m half
    const int mb   = half * 64 + 2 * lane;     // this thread's m pair
    const int b0   = blockIdx.x * BT;

    if (tid == 0) { *deltabits = 0u; *xmaxb = 0u; *okpos = 1; }
    __syncthreads();

    // ---- Whh -> Ws[k][m]; fold in rowsum partials + nonneg check ----
    {
        const int m = tid & 127, grp = tid >> 7;        // grp 0..3
        float rsum = 0.0f;
        bool nonneg = true;
        #pragma unroll
        for (int it = 0; it < 8; ++it) {
            int i  = tid + it * NTHR;                   // m stays == tid&127
            int kq = i >> 7;
            float4 v = *(const float4*)(Whh + (size_t)m * HD + 4 * kq);
            rsum += (v.x + v.y) + (v.z + v.w);
            nonneg &= (v.x >= 0.f) & (v.y >= 0.f) & (v.z >= 0.f) & (v.w >= 0.f);
            float vv[4] = {v.x, v.y, v.z, v.w};
            #pragma unroll
            for (int q = 0; q < 4; ++q)
                *(float*)(sm + SM_W + (4 * kq + q) * 512 + m * 4) = vv[q];
        }
        part[grp * 128 + m] = rsum;
        if (!nonneg) atomicAnd(okpos, 0);
    }
    // ---- x: streaming max over all t (MLP 8); store t < TPREF ----
    {
        float lm = 0.0f;
        #pragma unroll
        for (int it = 0; it < 8; ++it) {
            int i = tid + it * NTHR;
            int b = i >> 7, tq = i & 127;
            float4 v = *(const float4*)(x + (size_t)(b0 + b) * TS + 4 * tq);
            lm = fmaxf(lm, fmaxf(fmaxf(fabsf(v.x), fabsf(v.y)),
                                 fmaxf(fabsf(v.z), fabsf(v.w))));
            if (tq < TPREF / 4)
                *(float4*)(Xs + b * TPREF + 4 * tq) = v;
        }
        atomicMax(xmaxb, __float_as_uint(lm));           // |x| bits order-preserving
    }
    __syncthreads();

    // ---- adaptive certificate: delta* = max_m (10+c_m)/rowsum_m ----
    if (tid < HD) {
        int m = tid;
        float rs = part[m] + part[128 + m] + part[256 + m] + part[384 + m];
        float c  = fabsf(Whx[m]) * __uint_as_float(*xmaxb) + fabsf(bh[m]);
        float ratio = (rs > 0.0f) ? (10.0f + c) / rs : 2.0f;
        atomicMax(deltabits, __float_as_uint(ratio));    // positive floats
    }
    __syncthreads();
    const float dstar    = __uint_as_float(*deltabits);
    const bool  exact_ok = (dstar <= 1.0f);
    const float thr      = (exact_ok && *okpos) ? fmaxf(dstar, 0.05f) : 1.0f;

    const float2 wxv = *(const float2*)(Whx + mb);
    const float2 bhv = *(const float2*)(bh  + mb);
    const ull wx2 = pk(wxv.x, wxv.y);
    const ull bh2 = pk(bhv.x, bhv.y);
    const uint32_t sb    = smem_u32(sm);
    const uint32_t wbase = sb + SM_W + (uint32_t)(256 * half + 8 * lane);

    // ================= per-pair recurrence (named-barrier scoped) =================
    int cols[4] = {4 * pair, 4 * pair + 1, 4 * pair + 2, 4 * pair + 3};
    int nact = 4, cur = 0;

    for (int t = 0; t < TS && nact > 0; ++t) {
        const uint32_t hrd = sb + SM_HD + (uint32_t)cur * 32768u;
        float* hwr = (cur == 0) ? Hd1 : Hd0;

        float xv[4] = {0.f, 0.f, 0.f, 0.f};
        #pragma unroll
        for (int j = 0; j < 4; ++j)
            if (j < nact)
                xv[j] = (t < TPREF) ? Xs[cols[j] * TPREF + t]
                                    : __ldg(x + (size_t)(b0 + cols[j]) * TS + t);
        unsigned am;
        if (t == 0) {
            // h0 = 0: h1 = tanh(Whx*x0 + bh), no GEMV
            ull a[4];
            #pragma unroll
            for (int j = 0; j < 4; ++j)
                a[j] = fma2(wx2, pk(xv[j], xv[j]), bh2);
            am = epilogue<4>(a, hwr, cols, mb, thr);
        } else switch (nact) {
            case 4: am = do_step<4>(wbase, hrd, hwr, cols, xv, wx2, bh2, mb, thr); break;
            case 3: am = do_step<3>(wbase, hrd, hwr, cols, xv, wx2, bh2, mb, thr); break;
            case 2: am = do_step<2>(wbase, hrd, hwr, cols, xv, wx2, bh2, mb, thr); break;
            default: am = do_step<1>(wbase, hrd, hwr, cols, xv, wx2, bh2, mb, thr); break;
        }

        if (lane == 0) sflag[(t & 1) * 16 + pair * 2 + half] = am;
        asm volatile("bar.sync %0, 64;" :: "r"(1 + pair) : "memory");
        unsigned f0 = sflag[(t & 1) * 16 + pair * 2 + 0];
        unsigned f1 = sflag[(t & 1) * 16 + pair * 2 + 1];
        cur ^= 1;

        // uniform |h| >= thr across ALL 128 m => next state exactly uniform
        // +-1 and absorbing (certified). Needs a true step remaining (t<TS-1).
        if (exact_ok && t < TS - 1) {
            unsigned amp = f0 & f1 & 0xFu;
            unsigned amn = (f0 >> 8) & (f1 >> 8) & 0xFu;
            unsigned ab  = (amp | amn) & ((1u << nact) - 1u);
            if (ab) {
                #pragma unroll
                for (int j = 0; j < 4; ++j)
                    if (j < nact && ((ab >> j) & 1u)) {
                        float s = ((amp >> j) & 1u) ? 1.0f : -1.0f;
                        float4 sv = make_float4(s, s, s, s);
                        *(float4*)(Hd0 + (cols[j] * HD + mb) * 2) = sv;
                        *(float4*)(Hd1 + (cols[j] * HD + mb) * 2) = sv;
                    }
                int nn = 0, nc[4];
                #pragma unroll
                for (int j = 0; j < 4; ++j)
                    if (j < nact && !((ab >> j) & 1u)) nc[nn++] = cols[j];
                nact = nn;
                #pragma unroll
                for (int j = 0; j < 4; ++j) cols[j] = (j < nn) ? nc[j] : 0;
            }
        }
    }
    // make pair-mate's post-barrier sign writes visible before projection
    asm volatile("bar.sync %0, 64;" :: "r"(1 + pair) : "memory");

    // ================= projection: warp handles 2 of its pair's columns =================
    const float* hf = (cur == 0) ? Hd0 : Hd1;
    {
        int c0 = 4 * pair + 2 * half, c1 = c0 + 1;
        const float* h0p = hf + c0 * HD * 2;
        const float* h1p = hf + c1 * HD * 2;
        float4 a0 = *(const float4*)(h0p + 8 * lane);        // (h,h) pairs
        float4 a1 = *(const float4*)(h0p + 8 * lane + 4);
        float4 b0q = *(const float4*)(h1p + 8 * lane);
        float4 b1q = *(const float4*)(h1p + 8 * lane + 4);
        #pragma unroll
        for (int cls = 0; cls < CD; ++cls) {
            const float4 wq = __ldg((const float4*)(Wph + cls * HD) + lane);
            float s0 = a0.x * wq.x + a0.z * wq.y + a1.x * wq.z + a1.z * wq.w;
            float s1 = b0q.x * wq.x + b0q.z * wq.y + b1q.x * wq.z + b1q.z * wq.w;
            #pragma unroll
            for (int o = 16; o > 0; o >>= 1) {
                s0 += __shfl_xor_sync(0xffffffffu, s0, o);
                s1 += __shfl_xor_sync(0xffffffffu, s1, o);
            }
            if (lane == 0) {
                float bpv = __ldg(bp + cls);
                out[(size_t)(b0 + c0) * CD + cls] = s0 + bpv;
                out[(size_t)(b0 + c1) * CD + cls] = s1 + bpv;
            }
        }
    }
}

extern "C" void kernel_launch(void* const* d_in, const int* in_sizes, int n_in,
                              void* d_out, int out_size) {
    const float* x   = (const float*)d_in[0];
    const float* Whx = (const float*)d_in[1];
    const float* Whh = (const float*)d_in[2];
    const float* Wph = (const float*)d_in[3];
    const float* bh  = (const float*)d_in[4];
    const float* bp  = (const float*)d_in[5];
    cudaFuncSetAttribute(rnn_kernel, cudaFuncAttributeMaxDynamicSharedMemorySize, SM_SZ);
    rnn_kernel<<<NCTA, NTHR, SM_SZ>>>(x, Whx, Whh, Wph, bh, bp, (float*)d_out);
}